// round 3
// baseline (speedup 1.0000x reference)
#include <cuda_runtime.h>
#include <cstdint>

#define HIDDEN 2048
#define INTER  5504
#define TSTEPS 4
#define MROWS  4096   /* T*BSZ*SEQ */
#define BSROWS 1024   /* BSZ*SEQ */

#define STAGES      3
#define STAGE_BYTES 32768                  /* A 16KB + B 16KB */
#define DYN_SMEM    (STAGES * STAGE_BYTES) /* 96 KB */

// ---------------- scratch (device globals; no allocation allowed) ----------
__device__ float g_X [(size_t)MROWS * HIDDEN];
__device__ float g_WG[(size_t)INTER * HIDDEN];
__device__ float g_WU[(size_t)INTER * HIDDEN];
__device__ float g_WD[(size_t)HIDDEN * INTER];
__device__ float g_G [(size_t)MROWS * INTER];
__device__ float g_U [(size_t)MROWS * INTER];

// ---------------- helpers ----------------------------------------------------
__device__ __forceinline__ uint32_t smem_u32(const void* p) {
    uint32_t a;
    asm("{ .reg .u64 t; cvta.to.shared.u64 t, %1; cvt.u32.u64 %0, t; }" : "=r"(a) : "l"(p));
    return a;
}
__device__ __forceinline__ uint32_t f2tf32(float x) {
    uint32_t r; asm("cvt.rna.tf32.f32 %0, %1;" : "=r"(r) : "f"(x)); return r;
}
__device__ __forceinline__ float roundtf(float x) { return __uint_as_float(f2tf32(x)); }

#define CP_ASYNC16(dst, src) \
    asm volatile("cp.async.cg.shared.global [%0], [%1], 16;" :: "r"(dst), "l"(src))
#define CP_COMMIT() asm volatile("cp.async.commit_group;" ::: "memory")
#define CP_WAIT1()  asm volatile("cp.async.wait_group 1;"  ::: "memory")

__device__ __forceinline__ void mma_tf32(float* d, const uint32_t* a, const uint32_t* b) {
    asm volatile(
        "mma.sync.aligned.m16n8k8.row.col.f32.tf32.tf32.f32 "
        "{%0,%1,%2,%3}, {%4,%5,%6,%7}, {%8,%9}, {%0,%1,%2,%3};\n"
        : "+f"(d[0]), "+f"(d[1]), "+f"(d[2]), "+f"(d[3])
        : "r"(a[0]), "r"(a[1]), "r"(a[2]), "r"(a[3]), "r"(b[0]), "r"(b[1]));
}

// ---------------- GEMM: C[m,n] = sum_k A[m,k]*B[n,k] ------------------------
// A: M x K row-major, B: N x K row-major, both PRE-ROUNDED to tf32 (rna).
// C: M x N row-major fp32. Requires M%128==0 (grid.y), N%128==0 (grid.x), K%32==0.
// 256 threads, 2 CTAs/SM, 3-stage cp.async pipeline, 1 syncthreads per K-tile.
__global__ void __launch_bounds__(256, 2)
gemm_tn(const float* __restrict__ A, const float* __restrict__ B,
        float* __restrict__ C, int K, int N)
{
    extern __shared__ __align__(16) uint8_t smraw[];
    const uint32_t sb = smem_u32(smraw);

    const int tid  = threadIdx.x;
    const int lane = tid & 31;
    const int warp = tid >> 5;
    const int wm   = warp & 1;   // 2 warp rows of 64
    const int wn   = warp >> 1;  // 4 warp cols of 32

    const int r = tid >> 3;      // 0..31 : row within group of 32
    const int c = tid & 7;       // 0..7  : 16B (k4) chunk within 128B row

    const size_t mBase = (size_t)blockIdx.y * 128;
    const size_t nBase = (size_t)blockIdx.x * 128;
    const int NK = K >> 5;

    const float* Ag = A + (mBase + (size_t)r) * (size_t)K + (size_t)c * 4;
    const float* Bg = B + (nBase + (size_t)r) * (size_t)K + (size_t)c * 4;

    // smem stage layout: A atoms [k4(0..7)][m(0..127)] float4, slot m^k4; B at +16KB.
    auto fill = [&](int s, int kt) {
        const uint32_t abase = sb + s * STAGE_BYTES;
        const uint32_t bbase = abase + 16384;
        const float* Ak = Ag + (size_t)kt * 32;
        const float* Bk = Bg + (size_t)kt * 32;
        #pragma unroll
        for (int j = 0; j < 4; ++j) {
            const int m = j * 32 + r;
            const uint32_t slot = (uint32_t)(c * 128 + (m ^ c)) << 4;
            CP_ASYNC16(abase + slot, Ak + (size_t)(j * 32) * K);
            CP_ASYNC16(bbase + slot, Bk + (size_t)(j * 32) * K);
        }
    };

    fill(0, 0); CP_COMMIT();
    fill(1, 1); CP_COMMIT();

    float acc[4][4][4];
    #pragma unroll
    for (int i = 0; i < 4; ++i)
        #pragma unroll
        for (int j = 0; j < 4; ++j)
            #pragma unroll
            for (int q = 0; q < 4; ++q) acc[i][j][q] = 0.f;

    const int kk = lane & 3;
    const int g  = lane >> 2;

    for (int kt = 0; kt < NK; ++kt) {
        CP_WAIT1();          // stage kt resident (only kt+1 may remain in flight)
        __syncthreads();     // also guarantees stage (kt+2)%3 fully consumed

        if (kt + 2 < NK) fill((kt + 2) % STAGES, kt + 2);
        CP_COMMIT();         // empty groups at tail keep group numbering

        const int s = kt % STAGES;
        const uint32_t* Asw = reinterpret_cast<const uint32_t*>(smraw + s * STAGE_BYTES);
        const uint32_t* Bsw = Asw + 4096;

        #pragma unroll
        for (int ks = 0; ks < 4; ++ks) {
            const int k4a = ks * 2;
            const int k4b = ks * 2 + 1;

            uint32_t af[4][4];
            #pragma unroll
            for (int im = 0; im < 4; ++im) {
                const int m0 = wm * 64 + im * 16 + g;
                af[im][0] = Asw[(k4a * 128 + ((m0    ) ^ k4a)) * 4 + kk];
                af[im][1] = Asw[(k4a * 128 + ((m0 + 8) ^ k4a)) * 4 + kk];
                af[im][2] = Asw[(k4b * 128 + ((m0    ) ^ k4b)) * 4 + kk];
                af[im][3] = Asw[(k4b * 128 + ((m0 + 8) ^ k4b)) * 4 + kk];
            }
            uint32_t bf[4][2];
            #pragma unroll
            for (int jn = 0; jn < 4; ++jn) {
                const int n0 = wn * 32 + jn * 8 + g;
                bf[jn][0] = Bsw[(k4a * 128 + (n0 ^ k4a)) * 4 + kk];
                bf[jn][1] = Bsw[(k4b * 128 + (n0 ^ k4b)) * 4 + kk];
            }
            #pragma unroll
            for (int im = 0; im < 4; ++im)
                #pragma unroll
                for (int jn = 0; jn < 4; ++jn)
                    mma_tf32(acc[im][jn], af[im], bf[jn]);
        }
    }

    // Epilogue: fragment layout -> global (float2 per half-row).
    const int q2 = (lane & 3) * 2;
    #pragma unroll
    for (int im = 0; im < 4; ++im) {
        const size_t row0 = mBase + wm * 64 + im * 16 + g;
        #pragma unroll
        for (int jn = 0; jn < 4; ++jn) {
            const size_t col0 = nBase + wn * 32 + jn * 8 + q2;
            *(float2*)&C[row0 * (size_t)N + col0] =
                make_float2(acc[im][jn][0], acc[im][jn][1]);
            *(float2*)&C[(row0 + 8) * (size_t)N + col0] =
                make_float2(acc[im][jn][2], acc[im][jn][3]);
        }
    }
}

// ---------------- prepass: tf32-rna rounding --------------------------------
__global__ void round_copy_k(const float* __restrict__ src, float* __restrict__ dst, long n4)
{
    long i = (long)blockIdx.x * blockDim.x + threadIdx.x;
    if (i >= n4) return;
    float4 v = *(const float4*)(src + i * 4);
    *(float4*)(dst + i * 4) =
        make_float4(roundtf(v.x), roundtf(v.y), roundtf(v.z), roundtf(v.w));
}

// ---------------- combine: cumsum/silu/delta + closed-form Hadamard ---------
// Writes C (tf32-rounded, ready as down-GEMM operand) in place into g_G.
__global__ void combine_kernel()
{
    const size_t total  = (size_t)BSROWS * INTER;
    const size_t stride = total;
    size_t idx = (size_t)blockIdx.x * blockDim.x + threadIdx.x;
    if (idx >= total) return;

    float gv[TSTEPS], uv[TSTEPS];
    #pragma unroll
    for (int t = 0; t < TSTEPS; ++t) {
        gv[t] = g_G[idx + (size_t)t * stride];
        uv[t] = g_U[idx + (size_t)t * stride];
    }

    float X = 0.f, Yprev = 0.f, SB = 0.f;
    float Av[TSTEPS];
    #pragma unroll
    for (int t = 0; t < TSTEPS; ++t) {
        X += gv[t];
        const float Y = X / (1.f + expf(-X));  // silu
        Av[t] = Y - Yprev;
        Yprev = Y;
        SB += uv[t];
    }
    const float SA = Yprev;  // telescoping: sum_t A[t] = Y[T-1]

    #pragma unroll
    for (int t = 0; t < TSTEPS; ++t)
        g_G[idx + (size_t)t * stride] = roundtf(0.5f * (Av[t] * SB + uv[t] * SA));
}

// ---------------- launch -----------------------------------------------------
extern "C" void kernel_launch(void* const* d_in, const int* in_sizes, int n_in,
                              void* d_out, int out_size)
{
    const float* x      = (const float*)d_in[0];
    const float* w_gate = (const float*)d_in[1];
    const float* w_up   = (const float*)d_in[2];
    const float* w_down = (const float*)d_in[3];
    float* out = (float*)d_out;
    (void)in_sizes; (void)n_in; (void)out_size;

    float *dX, *dWG, *dWU, *dWD, *dG, *dU;
    cudaGetSymbolAddress((void**)&dX,  g_X);
    cudaGetSymbolAddress((void**)&dWG, g_WG);
    cudaGetSymbolAddress((void**)&dWU, g_WU);
    cudaGetSymbolAddress((void**)&dWD, g_WD);
    cudaGetSymbolAddress((void**)&dG,  g_G);
    cudaGetSymbolAddress((void**)&dU,  g_U);

    cudaFuncSetAttribute(gemm_tn, cudaFuncAttributeMaxDynamicSharedMemorySize, DYN_SMEM);

    // Prepass: tf32-rna round operands once (GEMM inner loop is CVT-free).
    {
        long n4 = (long)MROWS * HIDDEN / 4;
        round_copy_k<<<(unsigned)((n4 + 255) / 256), 256>>>(x, dX, n4);
        long w4 = (long)INTER * HIDDEN / 4;
        round_copy_k<<<(unsigned)((w4 + 255) / 256), 256>>>(w_gate, dWG, w4);
        round_copy_k<<<(unsigned)((w4 + 255) / 256), 256>>>(w_up,   dWU, w4);
        round_copy_k<<<(unsigned)((w4 + 255) / 256), 256>>>(w_down, dWD, w4);
    }

    // Gate / up projections: (4096 x 5504) = x(4096x2048) @ W^T
    {
        dim3 grid(INTER / 128, MROWS / 128);   // 43 x 32
        gemm_tn<<<grid, 256, DYN_SMEM>>>(dX, dWG, dG, HIDDEN, INTER);
        gemm_tn<<<grid, 256, DYN_SMEM>>>(dX, dWU, dU, HIDDEN, INTER);
    }

    // Combine (C -> g_G, rounded for the next GEMM).
    {
        size_t total = (size_t)BSROWS * INTER;
        combine_kernel<<<(unsigned)((total + 255) / 256), 256>>>();
    }

    // Down projection: (4096 x 2048) = C(4096x5504) @ w_down^T
    {
        dim3 grid(HIDDEN / 128, MROWS / 128);  // 16 x 32
        gemm_tn<<<grid, 256, DYN_SMEM>>>(dG, dWD, out, INTER, HIDDEN);
    }
}

// round 4
// speedup vs baseline: 1.0660x; 1.0660x over previous
#include <cuda_runtime.h>
#include <cstdint>

#define HIDDEN 2048
#define INTER  5504
#define TSTEPS 4
#define MROWS  4096   /* T*BSZ*SEQ */
#define BSROWS 1024   /* BSZ*SEQ */

#define STAGES      3
#define STAGE_BYTES 32768                  /* A 16KB + B 16KB */
#define DYN_SMEM    (STAGES * STAGE_BYTES) /* 96 KB -> 2 CTAs/SM = 192KB */

// ---------------- scratch (device globals; no allocation allowed) ----------
__device__ float g_X [(size_t)MROWS * HIDDEN];
__device__ float g_WG[(size_t)INTER * HIDDEN];
__device__ float g_WU[(size_t)INTER * HIDDEN];
__device__ float g_WD[(size_t)HIDDEN * INTER];
__device__ float g_G [(size_t)MROWS * INTER];
__device__ float g_U [(size_t)MROWS * INTER];

// ---------------- helpers ----------------------------------------------------
__device__ __forceinline__ uint32_t smem_u32(const void* p) {
    uint32_t a;
    asm("{ .reg .u64 t; cvta.to.shared.u64 t, %1; cvt.u32.u64 %0, t; }" : "=r"(a) : "l"(p));
    return a;
}
__device__ __forceinline__ uint32_t f2tf32(float x) {
    uint32_t r; asm("cvt.rna.tf32.f32 %0, %1;" : "=r"(r) : "f"(x)); return r;
}
__device__ __forceinline__ float roundtf(float x) { return __uint_as_float(f2tf32(x)); }

#define CP_ASYNC16(dst, src) \
    asm volatile("cp.async.cg.shared.global [%0], [%1], 16;" :: "r"(dst), "l"(src))
#define CP_COMMIT() asm volatile("cp.async.commit_group;" ::: "memory")
#define CP_WAIT1()  asm volatile("cp.async.wait_group 1;"  ::: "memory")

// ldmatrix x4: loads 4 8x(16B) matrices; works for tf32 (4B words) — each thread
// receives word (lane%4) of row (lane/4) of its matrix. Matches mma tf32 fragments.
#define LDSM_X4(r0, r1, r2, r3, addr) \
    asm volatile("ldmatrix.sync.aligned.m8n8.x4.shared.b16 {%0,%1,%2,%3}, [%4];" \
                 : "=r"(r0), "=r"(r1), "=r"(r2), "=r"(r3) : "r"(addr))

__device__ __forceinline__ void mma_tf32(float* d, const uint32_t* a, const uint32_t* b) {
    asm volatile(
        "mma.sync.aligned.m16n8k8.row.col.f32.tf32.tf32.f32 "
        "{%0,%1,%2,%3}, {%4,%5,%6,%7}, {%8,%9}, {%0,%1,%2,%3};\n"
        : "+f"(d[0]), "+f"(d[1]), "+f"(d[2]), "+f"(d[3])
        : "r"(a[0]), "r"(a[1]), "r"(a[2]), "r"(a[3]), "r"(b[0]), "r"(b[1]));
}

// ---------------- GEMM: C[m,n] = sum_k A[m,k]*B[n,k] ------------------------
// A: M x K row-major, B: N x K row-major, both PRE-ROUNDED to tf32 (rna).
// Requires M%128==0 (grid.y), N%128==0 (grid.x), K%32==0.
// 256 threads, 2 CTAs/SM, 3-stage cp.async, ldmatrix fragment loads.
__global__ void __launch_bounds__(256, 2)
gemm_tn(const float* __restrict__ A, const float* __restrict__ B,
        float* __restrict__ C, int K, int N)
{
    extern __shared__ __align__(16) uint8_t smraw[];
    const uint32_t sb = smem_u32(smraw);

    const int tid  = threadIdx.x;
    const int lane = tid & 31;
    const int warp = tid >> 5;
    const int wm   = warp & 1;   // 2 warp rows of 64
    const int wn   = warp >> 1;  // 4 warp cols of 32

    // cp.async fill mapping
    const int r = tid >> 3;      // 0..31 : row within group of 32
    const int c = tid & 7;       // 0..7  : 16B (k4) chunk within 128B row

    // ldmatrix per-lane row selectors (see fragment mapping in theory):
    //  A: m = wm*64 + im*16 + ((lane>>3)&1)*8 + (lane&7), k4 = ks*2 + (lane>>4)
    //  B: n = wn*32 + p*16  + (lane>>4)*8     + (lane&7), k4 = ks*2 + ((lane>>3)&1)
    const int rsel    = lane & 7;
    const int a_k4hi  = lane >> 4;
    const int a_moff  = ((lane >> 3) & 1) << 3;
    const int b_k4lo  = (lane >> 3) & 1;
    const int b_noff  = (lane >> 4) << 3;
    const int mrowA   = wm * 64 + a_moff + rsel;
    const int nrowB   = wn * 32 + b_noff + rsel;

    const size_t mBase = (size_t)blockIdx.y * 128;
    const size_t nBase = (size_t)blockIdx.x * 128;
    const int NK = K >> 5;

    const float* Ag = A + (mBase + (size_t)r) * (size_t)K + (size_t)c * 4;
    const float* Bg = B + (nBase + (size_t)r) * (size_t)K + (size_t)c * 4;

    // smem stage: A atoms [k4(0..7)][m(0..127)] float4 at slot m^k4; B at +16KB.
    auto fill = [&](int s, int kt) {
        const uint32_t abase = sb + s * STAGE_BYTES;
        const uint32_t bbase = abase + 16384;
        const float* Ak = Ag + (size_t)kt * 32;
        const float* Bk = Bg + (size_t)kt * 32;
        #pragma unroll
        for (int j = 0; j < 4; ++j) {
            const int m = j * 32 + r;
            const uint32_t slot = (uint32_t)(c * 128 + (m ^ c)) << 4;
            CP_ASYNC16(abase + slot, Ak + (size_t)(j * 32) * K);
            CP_ASYNC16(bbase + slot, Bk + (size_t)(j * 32) * K);
        }
    };

    fill(0, 0); CP_COMMIT();
    fill(1, 1); CP_COMMIT();

    float acc[4][4][4];
    #pragma unroll
    for (int i = 0; i < 4; ++i)
        #pragma unroll
        for (int j = 0; j < 4; ++j)
            #pragma unroll
            for (int q = 0; q < 4; ++q) acc[i][j][q] = 0.f;

    for (int kt = 0; kt < NK; ++kt) {
        CP_WAIT1();          // stage kt resident
        __syncthreads();     // stage (kt+2)%3 fully consumed by all warps

        if (kt + 2 < NK) fill((kt + 2) % STAGES, kt + 2);
        CP_COMMIT();         // empty tail groups keep numbering

        const uint32_t abase = sb + (kt % STAGES) * STAGE_BYTES;
        const uint32_t bbase = abase + 16384;

        #pragma unroll
        for (int ks = 0; ks < 4; ++ks) {
            const uint32_t ak4 = (uint32_t)(ks * 2 + a_k4hi);
            const uint32_t bk4 = (uint32_t)(ks * 2 + b_k4lo);

            uint32_t af[4][4];
            #pragma unroll
            for (int im = 0; im < 4; ++im) {
                const uint32_t m = (uint32_t)(mrowA + im * 16);
                const uint32_t addr = abase + (ak4 << 11) + (((m ^ ak4) & 127u) << 4);
                LDSM_X4(af[im][0], af[im][1], af[im][2], af[im][3], addr);
            }
            uint32_t bf[4][2];
            #pragma unroll
            for (int p = 0; p < 2; ++p) {
                const uint32_t n = (uint32_t)(nrowB + p * 16);
                const uint32_t addr = bbase + (bk4 << 11) + (((n ^ bk4) & 127u) << 4);
                LDSM_X4(bf[2 * p][0], bf[2 * p][1], bf[2 * p + 1][0], bf[2 * p + 1][1], addr);
            }
            #pragma unroll
            for (int im = 0; im < 4; ++im)
                #pragma unroll
                for (int jn = 0; jn < 4; ++jn)
                    mma_tf32(acc[im][jn], af[im], bf[jn]);
        }
    }

    // Epilogue: fragment layout -> global (float2 per half-row).
    const int g  = lane >> 2;
    const int q2 = (lane & 3) * 2;
    #pragma unroll
    for (int im = 0; im < 4; ++im) {
        const size_t row0 = mBase + wm * 64 + im * 16 + g;
        #pragma unroll
        for (int jn = 0; jn < 4; ++jn) {
            const size_t col0 = nBase + wn * 32 + jn * 8 + q2;
            *(float2*)&C[row0 * (size_t)N + col0] =
                make_float2(acc[im][jn][0], acc[im][jn][1]);
            *(float2*)&C[(row0 + 8) * (size_t)N + col0] =
                make_float2(acc[im][jn][2], acc[im][jn][3]);
        }
    }
}

// ---------------- prepass: tf32-rna rounding --------------------------------
__global__ void round_copy_k(const float* __restrict__ src, float* __restrict__ dst, long n4)
{
    long i = (long)blockIdx.x * blockDim.x + threadIdx.x;
    if (i >= n4) return;
    float4 v = *(const float4*)(src + i * 4);
    *(float4*)(dst + i * 4) =
        make_float4(roundtf(v.x), roundtf(v.y), roundtf(v.z), roundtf(v.w));
}

// ---------------- combine: cumsum/silu/delta + closed-form Hadamard ---------
__global__ void combine_kernel()
{
    const size_t total  = (size_t)BSROWS * INTER;
    const size_t stride = total;
    size_t idx = (size_t)blockIdx.x * blockDim.x + threadIdx.x;
    if (idx >= total) return;

    float gv[TSTEPS], uv[TSTEPS];
    #pragma unroll
    for (int t = 0; t < TSTEPS; ++t) {
        gv[t] = g_G[idx + (size_t)t * stride];
        uv[t] = g_U[idx + (size_t)t * stride];
    }

    float X = 0.f, Yprev = 0.f, SB = 0.f;
    float Av[TSTEPS];
    #pragma unroll
    for (int t = 0; t < TSTEPS; ++t) {
        X += gv[t];
        const float Y = X / (1.f + expf(-X));  // silu
        Av[t] = Y - Yprev;
        Yprev = Y;
        SB += uv[t];
    }
    const float SA = Yprev;  // telescoping: sum_t A[t] = Y[T-1]

    #pragma unroll
    for (int t = 0; t < TSTEPS; ++t)
        g_G[idx + (size_t)t * stride] = roundtf(0.5f * (Av[t] * SB + uv[t] * SA));
}

// ---------------- launch -----------------------------------------------------
extern "C" void kernel_launch(void* const* d_in, const int* in_sizes, int n_in,
                              void* d_out, int out_size)
{
    const float* x      = (const float*)d_in[0];
    const float* w_gate = (const float*)d_in[1];
    const float* w_up   = (const float*)d_in[2];
    const float* w_down = (const float*)d_in[3];
    float* out = (float*)d_out;
    (void)in_sizes; (void)n_in; (void)out_size;

    float *dX, *dWG, *dWU, *dWD, *dG, *dU;
    cudaGetSymbolAddress((void**)&dX,  g_X);
    cudaGetSymbolAddress((void**)&dWG, g_WG);
    cudaGetSymbolAddress((void**)&dWU, g_WU);
    cudaGetSymbolAddress((void**)&dWD, g_WD);
    cudaGetSymbolAddress((void**)&dG,  g_G);
    cudaGetSymbolAddress((void**)&dU,  g_U);

    cudaFuncSetAttribute(gemm_tn, cudaFuncAttributeMaxDynamicSharedMemorySize, DYN_SMEM);

    // Prepass: tf32-rna round operands once (GEMM inner loop is CVT-free).
    {
        long n4 = (long)MROWS * HIDDEN / 4;
        round_copy_k<<<(unsigned)((n4 + 255) / 256), 256>>>(x, dX, n4);
        long w4 = (long)INTER * HIDDEN / 4;
        round_copy_k<<<(unsigned)((w4 + 255) / 256), 256>>>(w_gate, dWG, w4);
        round_copy_k<<<(unsigned)((w4 + 255) / 256), 256>>>(w_up,   dWU, w4);
        round_copy_k<<<(unsigned)((w4 + 255) / 256), 256>>>(w_down, dWD, w4);
    }

    // Gate / up projections: (4096 x 5504) = x(4096x2048) @ W^T
    {
        dim3 grid(INTER / 128, MROWS / 128);   // 43 x 32
        gemm_tn<<<grid, 256, DYN_SMEM>>>(dX, dWG, dG, HIDDEN, INTER);
        gemm_tn<<<grid, 256, DYN_SMEM>>>(dX, dWU, dU, HIDDEN, INTER);
    }

    // Combine (C -> g_G, rounded for the next GEMM).
    {
        size_t total = (size_t)BSROWS * INTER;
        combine_kernel<<<(unsigned)((total + 255) / 256), 256>>>();
    }

    // Down projection: (4096 x 2048) = C(4096x5504) @ w_down^T
    {
        dim3 grid(HIDDEN / 128, MROWS / 128);  // 16 x 32
        gemm_tn<<<grid, 256, DYN_SMEM>>>(dG, dWD, out, INTER, HIDDEN);
    }
}